// round 1
// baseline (speedup 1.0000x reference)
#include <cuda_runtime.h>

#define THREADS 256
#define NWARP 8
#define AGB 4
#define STG_STRIDE 1312   // floats of staging per warp (4*320 x-area + 16 mask + pad)

typedef unsigned long long u64;

// ---- packed f32x2 helpers (sm_100+ PTX) ----
__device__ __forceinline__ u64 pk2(float lo, float hi) {
    u64 r; asm("mov.b64 %0, {%1,%2};" : "=l"(r) : "f"(lo), "f"(hi)); return r;
}
__device__ __forceinline__ float2 upk2(u64 v) {
    float2 f; asm("mov.b64 {%0,%1}, %2;" : "=f"(f.x), "=f"(f.y) : "l"(v)); return f;
}
__device__ __forceinline__ void fma2(u64 &d, u64 a, u64 b) {
    asm("fma.rn.f32x2 %0, %1, %2, %0;" : "+l"(d) : "l"(a), "l"(b));
}

// Fused GAT layer.
// Column ownership: lane l owns output cols 4l..4l+3 of the 128-wide head space
// (both for the agent projection and, via interleaved Wc layout, for the
// neighbor nr/nh projections). Head of lane l = l>>3, so 8-lane shfl groups
// reduce attention dots.
__global__ __launch_bounds__(THREADS, 1)
void gat_kernel(const float* __restrict__ agent,
                const float* __restrict__ neighbor,
                const int*   __restrict__ nmask,
                const float* __restrict__ Wa_g, const float* __restrict__ ba_g,
                const float* __restrict__ Wn_g, const float* __restrict__ bn_g,
                const float* __restrict__ Wh_g, const float* __restrict__ bh_g,
                const float* __restrict__ Wo_g, const float* __restrict__ bo_g,
                float* __restrict__ out, int n)
{
    extern __shared__ float sm[];
    float* sWa  = sm;                  // [64][128]
    float* sWc  = sWa + 64 * 128;      // [64][256]  interleaved nr|nh per 8-col group
    float* sWo  = sWc + 64 * 256;      // [128][64]
    float* sba  = sWo + 128 * 64;      // [128]
    float* sbc  = sba + 128;           // [256] interleaved like sWc
    float* sbo  = sbc + 256;           // [64]
    float* sStg = sbo + 64;            // NWARP * STG_STRIDE

    const int tid  = threadIdx.x;
    const int lane = tid & 31;
    const int wid  = tid >> 5;

    // ---- cache weights in SMEM ----
    for (int i = tid; i < 64 * 128; i += THREADS) sWa[i] = Wa_g[i];
    for (int i = tid; i < 128 * 64; i += THREADS) sWo[i] = Wo_g[i];
    for (int i = tid; i < 64 * 256; i += THREADS) {
        int k = i >> 8, c = i & 255;
        int l = c >> 3, t = c & 7;
        // cols 8l+t: t<4 -> W_neigh col 4l+t ; t>=4 -> W_hid col 4l+t-4
        sWc[i] = (t < 4) ? Wn_g[k * 128 + 4 * l + t] : Wh_g[k * 128 + 4 * l + t - 4];
    }
    for (int i = tid; i < 128; i += THREADS) sba[i] = ba_g[i];
    for (int i = tid; i < 256; i += THREADS) {
        int l = i >> 3, t = i & 7;
        sbc[i] = (t < 4) ? bn_g[4 * l + t] : bh_g[4 * l + t - 4];
    }
    for (int i = tid; i < 64; i += THREADS) sbo[i] = bo_g[i];
    __syncthreads();

    // per-lane bias registers (loop-invariant)
    const u64 biasA0 = pk2(sba[4 * lane + 0], sba[4 * lane + 1]);
    const u64 biasA1 = pk2(sba[4 * lane + 2], sba[4 * lane + 3]);
    u64 biasC[4];
#pragma unroll
    for (int t = 0; t < 4; ++t)
        biasC[t] = pk2(sbc[8 * lane + 2 * t], sbc[8 * lane + 2 * t + 1]);
    const u64 biasO = pk2(sbo[2 * lane], sbo[2 * lane + 1]);

    float* stg = sStg + wid * STG_STRIDE;

    const int gwarp   = blockIdx.x * NWARP + wid;
    const int nwarps  = gridDim.x * NWARP;
    const int ngroups = (n + AGB - 1) / AGB;

    for (int g = gwarp; g < ngroups; g += nwarps) {
        const int base = g * AGB;

        // ---- load x (agent + 4 neighbors) + masks into warp staging ----
#pragma unroll
        for (int a = 0; a < AGB; ++a) {
            int ia = min(base + a, n - 1);
            float2 v = *reinterpret_cast<const float2*>(agent + (size_t)ia * 64 + 2 * lane);
            *reinterpret_cast<float2*>(stg + a * 320 + 2 * lane) = v;
#pragma unroll
            for (int nb = 0; nb < 4; ++nb) {
                float2 w = *reinterpret_cast<const float2*>(
                    neighbor + (size_t)ia * 256 + nb * 64 + 2 * lane);
                *reinterpret_cast<float2*>(stg + a * 320 + 64 + nb * 64 + 2 * lane) = w;
            }
        }
        if (lane < 16) {
            int a = lane >> 2, nb = lane & 3;
            int ia = min(base + a, n - 1);
            stg[1280 + lane] = (float)nmask[(size_t)ia * 4 + nb];
        }
        __syncwarp();

        // ---- stage 1: a = relu(x@Wa+b), nr|nh = relu(xn@Wc+b) for 4 neighbors ----
        u64 accA[AGB][2];
        u64 accN[AGB][4][4];   // [agent][neighbor][pair]: pairs 0,1 = nr cols, 2,3 = nh cols
#pragma unroll
        for (int a = 0; a < AGB; ++a) {
            accA[a][0] = biasA0; accA[a][1] = biasA1;
#pragma unroll
            for (int nb = 0; nb < 4; ++nb)
#pragma unroll
                for (int t = 0; t < 4; ++t) accN[a][nb][t] = biasC[t];
        }

#pragma unroll 1
        for (int k2 = 0; k2 < 32; ++k2) {
            const int k0 = 2 * k2, k1 = 2 * k2 + 1;
            ulonglong2 WA0  = *reinterpret_cast<const ulonglong2*>(sWa + k0 * 128 + 4 * lane);
            ulonglong2 WA1  = *reinterpret_cast<const ulonglong2*>(sWa + k1 * 128 + 4 * lane);
            ulonglong2 WC00 = *reinterpret_cast<const ulonglong2*>(sWc + k0 * 256 + 8 * lane);
            ulonglong2 WC01 = *reinterpret_cast<const ulonglong2*>(sWc + k0 * 256 + 8 * lane + 4);
            ulonglong2 WC10 = *reinterpret_cast<const ulonglong2*>(sWc + k1 * 256 + 8 * lane);
            ulonglong2 WC11 = *reinterpret_cast<const ulonglong2*>(sWc + k1 * 256 + 8 * lane + 4);
#pragma unroll
            for (int a = 0; a < AGB; ++a) {
                const float* xa = stg + a * 320;
                float2 xv = *reinterpret_cast<const float2*>(xa + k0);
                u64 x0 = pk2(xv.x, xv.x), x1 = pk2(xv.y, xv.y);
                fma2(accA[a][0], WA0.x, x0); fma2(accA[a][1], WA0.y, x0);
                fma2(accA[a][0], WA1.x, x1); fma2(accA[a][1], WA1.y, x1);
#pragma unroll
                for (int nb = 0; nb < 4; ++nb) {
                    float2 nv = *reinterpret_cast<const float2*>(xa + 64 + nb * 64 + k0);
                    u64 n0 = pk2(nv.x, nv.x), n1 = pk2(nv.y, nv.y);
                    fma2(accN[a][nb][0], WC00.x, n0); fma2(accN[a][nb][1], WC00.y, n0);
                    fma2(accN[a][nb][2], WC01.x, n0); fma2(accN[a][nb][3], WC01.y, n0);
                    fma2(accN[a][nb][0], WC10.x, n1); fma2(accN[a][nb][1], WC10.y, n1);
                    fma2(accN[a][nb][2], WC11.x, n1); fma2(accN[a][nb][3], WC11.y, n1);
                }
            }
        }
        __syncwarp();  // all staging x reads done before H overwrites it

        // ---- stage 2: attention + softmax + weighted mean; H -> staging ----
#pragma unroll
        for (int a = 0; a < AGB; ++a) {
            float av[4];
            {
                float2 t0 = upk2(accA[a][0]), t1 = upk2(accA[a][1]);
                av[0] = fmaxf(t0.x, 0.f); av[1] = fmaxf(t0.y, 0.f);
                av[2] = fmaxf(t1.x, 0.f); av[3] = fmaxf(t1.y, 0.f);
            }
            float nr[4][4], nh[4][4];
#pragma unroll
            for (int nb = 0; nb < 4; ++nb) {
                float2 r0 = upk2(accN[a][nb][0]), r1 = upk2(accN[a][nb][1]);
                float2 h0 = upk2(accN[a][nb][2]), h1 = upk2(accN[a][nb][3]);
                nr[nb][0] = fmaxf(r0.x, 0.f); nr[nb][1] = fmaxf(r0.y, 0.f);
                nr[nb][2] = fmaxf(r1.x, 0.f); nr[nb][3] = fmaxf(r1.y, 0.f);
                nh[nb][0] = fmaxf(h0.x, 0.f); nh[nb][1] = fmaxf(h0.y, 0.f);
                nh[nb][2] = fmaxf(h1.x, 0.f); nh[nb][3] = fmaxf(h1.y, 0.f);
            }
            float p[4];
#pragma unroll
            for (int nb = 0; nb < 4; ++nb) {
                p[nb] = av[0] * nr[nb][0] + av[1] * nr[nb][1] +
                        av[2] * nr[nb][2] + av[3] * nr[nb][3];
            }
            // reduce partial dots over the 8-lane head group
#pragma unroll
            for (int off = 1; off < 8; off <<= 1) {
#pragma unroll
                for (int nb = 0; nb < 4; ++nb)
                    p[nb] += __shfl_xor_sync(0xffffffffu, p[nb], off);
            }
            float mk[4], lg[4];
#pragma unroll
            for (int nb = 0; nb < 4; ++nb) {
                mk[nb] = stg[1280 + a * 4 + nb];
                lg[nb] = fmaf(mk[nb], -1e8f, p[nb]);
            }
            float m = fmaxf(fmaxf(lg[0], lg[1]), fmaxf(lg[2], lg[3]));
            float e[4];
            float s = 0.f;
#pragma unroll
            for (int nb = 0; nb < 4; ++nb) { e[nb] = __expf(lg[nb] - m); s += e[nb]; }
            float inv = 0.25f / s;  // fold the .mean(2) divide-by-4
            float sc[4];
#pragma unroll
            for (int nb = 0; nb < 4; ++nb) sc[nb] = (1.0f - mk[nb]) * e[nb] * inv;
            float h[4];
#pragma unroll
            for (int t = 0; t < 4; ++t)
                h[t] = sc[0] * nh[0][t] + sc[1] * nh[1][t] +
                       sc[2] * nh[2][t] + sc[3] * nh[3][t];
            *reinterpret_cast<float4*>(stg + a * 320 + 4 * lane) =
                make_float4(h[0], h[1], h[2], h[3]);
        }
        __syncwarp();

        // ---- stage 3: out = relu(H @ Wo + bo) ----
        u64 accO[AGB];
#pragma unroll
        for (int a = 0; a < AGB; ++a) accO[a] = biasO;
#pragma unroll 4
        for (int c2 = 0; c2 < 64; ++c2) {
            u64 wo0 = *reinterpret_cast<const u64*>(sWo + (2 * c2) * 64 + 2 * lane);
            u64 wo1 = *reinterpret_cast<const u64*>(sWo + (2 * c2 + 1) * 64 + 2 * lane);
#pragma unroll
            for (int a = 0; a < AGB; ++a) {
                float2 hv = *reinterpret_cast<const float2*>(stg + a * 320 + 2 * c2);
                fma2(accO[a], wo0, pk2(hv.x, hv.x));
                fma2(accO[a], wo1, pk2(hv.y, hv.y));
            }
        }

#pragma unroll
        for (int a = 0; a < AGB; ++a) {
            int idx = base + a;
            if (idx < n) {
                float2 r = upk2(accO[a]);
                r.x = fmaxf(r.x, 0.f);
                r.y = fmaxf(r.y, 0.f);
                *reinterpret_cast<float2*>(out + (size_t)idx * 64 + 2 * lane) = r;
            }
        }
    }
}

extern "C" void kernel_launch(void* const* d_in, const int* in_sizes, int n_in,
                              void* d_out, int out_size)
{
    const float* agent    = (const float*)d_in[0];
    const float* neighbor = (const float*)d_in[1];
    const int*   nmask    = (const int*)d_in[2];
    const float* Wa       = (const float*)d_in[3];
    const float* ba       = (const float*)d_in[4];
    const float* Wn       = (const float*)d_in[5];
    const float* bn       = (const float*)d_in[6];
    const float* Wh       = (const float*)d_in[7];
    const float* bh       = (const float*)d_in[8];
    const float* Wo       = (const float*)d_in[9];
    const float* bo       = (const float*)d_in[10];
    float* out = (float*)d_out;

    const int n = in_sizes[0] / 64;

    const size_t smem =
        (size_t)(64 * 128 + 64 * 256 + 128 * 64 + 128 + 256 + 64 + NWARP * STG_STRIDE)
        * sizeof(float);
    cudaFuncSetAttribute(gat_kernel, cudaFuncAttributeMaxDynamicSharedMemorySize,
                         (int)smem);

    int sms = 148;
    cudaDeviceGetAttribute(&sms, cudaDevAttrMultiProcessorCount, 0);
    const int ngroups = (n + AGB - 1) / AGB;
    int maxb = (ngroups + NWARP - 1) / NWARP;
    int grid = sms < maxb ? sms : maxb;
    if (grid < 1) grid = 1;

    gat_kernel<<<grid, THREADS, smem>>>(agent, neighbor, nmask,
                                        Wa, ba, Wn, bn, Wh, bh, Wo, bo,
                                        out, n);
}